// round 14
// baseline (speedup 1.0000x reference)
#include <cuda_runtime.h>
#include <cuda_fp16.h>

#define EMB   400
#define HID   300
#define HIDP  304
#define PHIS  312
#define KEY   128
#define VALD  128
#define VOCAB 33
#define TT    256
#define BB    256
#define SS    512

#define KP2   432
#define MROWS 1200
#define MPAD  1216
#define MPAD2 1280
#define NBLK  256
#define NSEG  12
#define SEGK  36
#define CHUNK 12
#define NPIECE 240

// ---------------- device scratch ----------------
__device__ float  g_Wt[(size_t)KP2 * MPAD2];
__device__ float  g_Z[KP2 * BB];
__device__ float  g_gpart[(size_t)NSEG * BB * MPAD2];
__device__ float  g_c[BB * HID];
__device__ float  g_gv[VOCAB * MPAD];
__device__ __half g_phiH[KEY * HIDP];
__device__ __half g_keysH[(size_t)BB * KEY * SS];
__device__ __half g_valsH[(size_t)BB * SS * VALD];
__device__ unsigned g_cnt;
__device__ unsigned g_gen;

// ---------------- shared memory ----------------
struct __align__(16) SMem {
    __half phi[KEY * PHIS];
    float h_s[HIDP];
    float q_s[KEY];
    float qp[256];
    float e_s[SS];
    float ctx_s[VALD];
    float red_s[8];
    union {
        struct { float Ws[CHUNK * 128]; float Zs[CHUNK * 128]; } g;
        float e4[4 * SS];
        float part[16 * VALD];
    } u;
};

// ---------------- helpers ----------------
__device__ __forceinline__ float warp_sum(float v) {
#pragma unroll
    for (int m = 16; m > 0; m >>= 1) v += __shfl_xor_sync(0xffffffffu, v, m);
    return v;
}
__device__ __forceinline__ float warp_max(float v) {
#pragma unroll
    for (int m = 16; m > 0; m >>= 1) v = fmaxf(v, __shfl_xor_sync(0xffffffffu, v, m));
    return v;
}
__device__ __forceinline__ float sigf(float x) { return 1.0f / (1.0f + __expf(-x)); }

__device__ __forceinline__ unsigned long long fma2(unsigned long long a,
                                                   unsigned long long b,
                                                   unsigned long long c) {
    unsigned long long d;
    asm("fma.rn.f32x2 %0, %1, %2, %3;" : "=l"(d) : "l"(a), "l"(b), "l"(c));
    return d;
}
__device__ __forceinline__ unsigned long long pack2(float x) {
    unsigned long long d;
    unsigned int xi = __float_as_uint(x);
    asm("mov.b64 %0, {%1, %1};" : "=l"(d) : "r"(xi));
    return d;
}
__device__ __forceinline__ unsigned long long f2u(float2 v) {
    unsigned long long d;
    asm("mov.b64 %0, {%1, %2};"
        : "=l"(d) : "r"(__float_as_uint(v.x)), "r"(__float_as_uint(v.y)));
    return d;
}
__device__ __forceinline__ float2 unpack2(unsigned long long v) {
    unsigned int lo, hi;
    asm("mov.b64 {%0, %1}, %2;" : "=r"(lo), "=r"(hi) : "l"(v));
    return make_float2(__uint_as_float(lo), __uint_as_float(hi));
}

// grid barrier via release/acquire atomics (no CCTL.IVALL — L1 stays warm).
__device__ __forceinline__ void gsync() {
    __syncthreads();
    if (threadIdx.x == 0) {
        unsigned my;
        asm volatile("ld.global.relaxed.gpu.u32 %0, [%1];"
                     : "=r"(my) : "l"(&g_gen) : "memory");
        unsigned rv;
        asm volatile("atom.global.add.acq_rel.gpu.u32 %0, [%1], 1;"
                     : "=r"(rv) : "l"(&g_cnt) : "memory");
        if (rv == NBLK - 1u) {
            asm volatile("st.global.relaxed.gpu.u32 [%0], 0;"
                         :: "l"(&g_cnt) : "memory");
            asm volatile("st.global.release.gpu.u32 [%0], %1;"
                         :: "l"(&g_gen), "r"(my + 1u) : "memory");
        } else {
            unsigned cur;
            do {
                asm volatile("ld.global.acquire.gpu.u32 %0, [%1];"
                             : "=r"(cur) : "l"(&g_gen) : "memory");
            } while (cur == my);
        }
    }
    __syncthreads();
}

// ---------------- attention (8 warps, packed f32x2 math) ----------------
__device__ void attention(SMem* sm, int b, int tid, const float* __restrict__ phi_b) {
    int warp = tid >> 5, lane = tid & 31;

    // q matvec: packed fma2, h pairs as u64
    {
        int kq = tid & 127;
        int hf = tid >> 7;
        const uint4* pw = (const uint4*)&sm->phi[kq * PHIS + hf * (HIDP / 2)];
        const ulonglong2* hp = (const ulonglong2*)&sm->h_s[hf * (HIDP / 2)];
        unsigned long long a0 = 0ull, a1 = 0ull;
#pragma unroll
        for (int u = 0; u < HIDP / 16; u++) {
            uint4 raw = pw[u];
            ulonglong2 ha = hp[u * 2];
            ulonglong2 hb = hp[u * 2 + 1];
            float2 f0 = __half22float2(*(const __half2*)&raw.x);
            float2 f1 = __half22float2(*(const __half2*)&raw.y);
            float2 f2 = __half22float2(*(const __half2*)&raw.z);
            float2 f3 = __half22float2(*(const __half2*)&raw.w);
            a0 = fma2(f2u(f0), ha.x, a0);
            a1 = fma2(f2u(f1), ha.y, a1);
            a0 = fma2(f2u(f2), hb.x, a0);
            a1 = fma2(f2u(f3), hb.y, a1);
        }
        float2 p0 = unpack2(a0), p1 = unpack2(a1);
        sm->qp[tid] = (p0.x + p0.y) + (p1.x + p1.y);
    }
    __syncthreads();
    if (tid < KEY) sm->q_s[tid] = sm->qp[tid] + sm->qp[tid + 128] + phi_b[tid];
    __syncthreads();

    // energy partials: thread = (kg, sg): 32 k x 8 s; packed fma2
    {
        int kg = tid >> 6;
        int sg = tid & 63;
        const uint4* kp = (const uint4*)&g_keysH[((size_t)b * KEY + kg * 32) * SS + sg * 8];
        unsigned long long a0 = 0ull, a1 = 0ull, a2 = 0ull, a3 = 0ull;
#pragma unroll 16
        for (int k = 0; k < 32; k++) {
            uint4 raw = kp[(size_t)k * (SS / 8)];
            unsigned long long qk2 = pack2(sm->q_s[kg * 32 + k]);
            float2 f0 = __half22float2(*(const __half2*)&raw.x);
            float2 f1 = __half22float2(*(const __half2*)&raw.y);
            float2 f2 = __half22float2(*(const __half2*)&raw.z);
            float2 f3 = __half22float2(*(const __half2*)&raw.w);
            a0 = fma2(qk2, f2u(f0), a0);
            a1 = fma2(qk2, f2u(f1), a1);
            a2 = fma2(qk2, f2u(f2), a2);
            a3 = fma2(qk2, f2u(f3), a3);
        }
        float2 p0 = unpack2(a0), p1 = unpack2(a1), p2 = unpack2(a2), p3 = unpack2(a3);
        *(float4*)&sm->u.e4[kg * SS + sg * 8]     = make_float4(p0.x, p0.y, p1.x, p1.y);
        *(float4*)&sm->u.e4[kg * SS + sg * 8 + 4] = make_float4(p2.x, p2.y, p3.x, p3.y);
    }
    __syncthreads();

    // fused combine + local max
    float m = -3.0e38f;
    for (int s = tid; s < SS; s += 256) {
        float v = sm->u.e4[s] + sm->u.e4[SS + s] + sm->u.e4[2 * SS + s] + sm->u.e4[3 * SS + s];
        sm->e_s[s] = v;
        m = fmaxf(m, v);
    }
    m = warp_max(m);
    if (lane == 0) sm->red_s[warp] = m;
    __syncthreads();
    float mf = sm->red_s[0];
#pragma unroll
    for (int i = 1; i < 8; i++) mf = fmaxf(mf, sm->red_s[i]);
    __syncthreads();
    float sum = 0.0f;
    for (int s = tid; s < SS; s += 256) {
        float v = __expf(sm->e_s[s] - mf);
        sm->e_s[s] = v;
        sum += v;
    }
    sum = warp_sum(sum);
    if (lane == 0) sm->red_s[warp] = sum;
    __syncthreads();
    float tot = sm->red_s[0];
#pragma unroll
    for (int i = 1; i < 8; i++) tot += sm->red_s[i];
    float inv = 1.0f / tot;
    __syncthreads();

    // ctx: packed fma2
    {
        int sh = lane >> 4;
        int dg = lane & 15;
        int sbase = warp * 64 + sh * 32;
        const uint4* vp = (const uint4*)&g_valsH[((size_t)b * SS + sbase) * VALD + dg * 8];
        unsigned long long a0 = 0ull, a1 = 0ull, a2 = 0ull, a3 = 0ull;
#pragma unroll 16
        for (int i = 0; i < 32; i++) {
            uint4 raw = vp[(size_t)i * (VALD / 8)];
            unsigned long long w2 = pack2(sm->e_s[sbase + i]);
            float2 f0 = __half22float2(*(const __half2*)&raw.x);
            float2 f1 = __half22float2(*(const __half2*)&raw.y);
            float2 f2 = __half22float2(*(const __half2*)&raw.z);
            float2 f3 = __half22float2(*(const __half2*)&raw.w);
            a0 = fma2(w2, f2u(f0), a0);
            a1 = fma2(w2, f2u(f1), a1);
            a2 = fma2(w2, f2u(f2), a2);
            a3 = fma2(w2, f2u(f3), a3);
        }
        float2 p0 = unpack2(a0), p1 = unpack2(a1), p2 = unpack2(a2), p3 = unpack2(a3);
        int prow = warp * 2 + sh;
        *(float4*)&sm->u.part[prow * VALD + dg * 8]     = make_float4(p0.x, p0.y, p1.x, p1.y);
        *(float4*)&sm->u.part[prow * VALD + dg * 8 + 4] = make_float4(p2.x, p2.y, p3.x, p3.y);
    }
    __syncthreads();
    if (tid < VALD) {
        float s = 0.0f;
#pragma unroll
        for (int w = 0; w < 16; w++) s += sm->u.part[w * VALD + tid];
        sm->ctx_s[tid] = s * inv;
    }
    __syncthreads();
}

// ---------------- persistent kernel ----------------
__global__ void __launch_bounds__(256, 2) kmain(const int* __restrict__ input,
                                                const float* __restrict__ keys,
                                                const float* __restrict__ values,
                                                const float* __restrict__ embedding,
                                                const float* __restrict__ phi_w,
                                                const float* __restrict__ phi_b,
                                                const float* __restrict__ h0,
                                                const float* __restrict__ c0,
                                                const float* __restrict__ W_ih,
                                                const float* __restrict__ b_ih,
                                                const float* __restrict__ W_hh,
                                                const float* __restrict__ b_hh,
                                                const float* __restrict__ proj_w,
                                                const float* __restrict__ proj_b,
                                                float* __restrict__ out) {
    extern __shared__ char smraw[];
    SMem* sm = (SMem*)smraw;

    int bid = blockIdx.x, tid = threadIdx.x;
    int warp = tid >> 5, lane = tid & 31;
    int b = bid;

    // ================= PROLOGUE =================
    {
        int gidx = bid * 256 + tid;
        const int gstr = NBLK * 256;
        for (size_t i = gidx; i < (size_t)KP2 * MPAD2; i += gstr) {
            int k = (int)(i / MPAD2), r = (int)(i % MPAD2);
            float v = 0.0f;
            if (r < MROWS) {
                if (k < VALD)            v = W_ih[r * (EMB + VALD) + EMB + k];
                else if (k < VALD + HID) v = W_hh[r * HID + (k - VALD)];
            }
            g_Wt[i] = v;
        }
        for (int i = gidx; i < KEY * HIDP; i += gstr) {
            int kq = i / HIDP, j = i % HIDP;
            g_phiH[i] = (j < HID) ? __float2half(phi_w[kq * HID + j]) : __half(0.0f);
        }
        for (int i = gidx; i < (KP2 - (VALD + HID)) * BB; i += gstr)
            g_Z[(VALD + HID) * BB + i] = 0.0f;

        float (*ts)[129] = (float (*)[129])smraw;
#pragma unroll 1
        for (int cth = 0; cth < 8; cth++) {
            int s0 = cth * 64;
            __syncthreads();
#pragma unroll
            for (int p = 0; p < 8; p++) {
                int i  = p * 8 + (tid >> 5);
                int k4 = (tid & 31) * 4;
                float4 v = *(const float4*)&keys[((size_t)(s0 + i) * BB + b) * KEY + k4];
                ts[i][k4] = v.x; ts[i][k4 + 1] = v.y; ts[i][k4 + 2] = v.z; ts[i][k4 + 3] = v.w;
            }
            __syncthreads();
#pragma unroll
            for (int p = 0; p < 8; p++) {
                int k  = p * 16 + (tid >> 4);
                int s4 = (tid & 15) * 4;
                __half2 a = __floats2half2_rn(ts[s4][k],     ts[s4 + 1][k]);
                __half2 c = __floats2half2_rn(ts[s4 + 2][k], ts[s4 + 3][k]);
                __half2* dst = (__half2*)&g_keysH[((size_t)b * KEY + k) * SS + s0 + s4];
                dst[0] = a; dst[1] = c;
            }
        }
#pragma unroll 1
        for (int cth = 0; cth < 8; cth++) {
            int s0 = cth * 64;
#pragma unroll
            for (int p = 0; p < 4; p++) {
                int item = p * 256 + tid;
                int row = item >> 4;
                int g   = item & 15;
                const float4* src = (const float4*)&values[((size_t)(s0 + row) * BB + b) * VALD + g * 8];
                float4 v0 = src[0], v1 = src[1];
                __half2 h0h = __floats2half2_rn(v0.x, v0.y);
                __half2 h1h = __floats2half2_rn(v0.z, v0.w);
                __half2 h2h = __floats2half2_rn(v1.x, v1.y);
                __half2 h3h = __floats2half2_rn(v1.z, v1.w);
                *(uint4*)&g_valsH[((size_t)b * SS + s0 + row) * VALD + g * 8] =
                    make_uint4(*(unsigned*)&h0h, *(unsigned*)&h1h, *(unsigned*)&h2h, *(unsigned*)&h3h);
            }
        }
        if (bid < 4 * VOCAB) {
            int v = bid >> 2;
            int rbase = (bid & 3) * 304;
            float* emb_s = (float*)smraw;
            __syncthreads();
            for (int e = tid; e < EMB; e += 256) emb_s[e] = embedding[v * EMB + e];
            __syncthreads();
            for (int r = rbase + warp; r < rbase + 304; r += 8) {
                float s = 0.0f;
                if (r < MROWS) {
                    const float* wr = &W_ih[(size_t)r * (EMB + VALD)];
                    for (int e = lane; e < EMB; e += 32) s = fmaf(wr[e], emb_s[e], s);
                }
                s = warp_sum(s);
                if (lane == 0)
                    g_gv[v * MPAD + r] = (r < MROWS) ? s + b_ih[r] + b_hh[r] : 0.0f;
            }
        }
    }
    gsync();

    // ================= INIT =================
    for (int item = tid; item < KEY * (HIDP / 8); item += 256) {
        int kq = item / (HIDP / 8);
        int u  = item % (HIDP / 8);
        *(uint4*)&sm->phi[kq * PHIS + u * 8] = *(const uint4*)&g_phiH[kq * HIDP + u * 8];
    }

    bool gemmOn = (bid < NPIECE);
    int gTile = bid / NSEG, gSeg = bid % NSEG;
    int rowBase = (gTile % 10) * 128;
    int colBase = (gTile / 10) * 128;
    int kBase = gSeg * SEGK;
    float* outbuf = g_gpart + (size_t)gSeg * (BB * MPAD2);
    int rg = tid & 15, cg = tid >> 4;
    int gr0 = rg * 8, gc0 = cg * 8;

    for (int j = tid; j < HIDP; j += 256) {
        sm->h_s[j] = (j < HID) ? h0[j] : 0.0f;
        if (j < HID) g_c[b * HID + j] = c0[j];
    }
    __syncthreads();
    attention(sm, b, tid, phi_b);
    for (int d = tid; d < VALD; d += 256) g_Z[d * BB + b] = sm->ctx_s[d];
    for (int j = tid; j < HID; j += 256)  g_Z[(VALD + j) * BB + b] = sm->h_s[j];
    gsync();

    // ================= MAIN LOOP =================
    for (int t = 0; t < TT; t++) {
        if (gemmOn) {
            unsigned long long acc[8][4];
#pragma unroll
            for (int c = 0; c < 8; c++)
#pragma unroll
                for (int r = 0; r < 4; r++) acc[c][r] = 0ull;

            float2 wpre[3], zpre[3];
#pragma unroll
            for (int i = 0; i < 3; i++) {
                int item = tid + 256 * i;
                int kk = item >> 6, off = (item & 63) * 2;
                wpre[i] = *(const float2*)&g_Wt[(size_t)(kBase + kk) * MPAD2 + rowBase + off];
                zpre[i] = __ldcg((const float2*)&g_Z[(kBase + kk) * BB + colBase + off]);
            }

#pragma unroll
            for (int chunk = 0; chunk < SEGK / CHUNK; chunk++) {
                __syncthreads();
#pragma unroll
                for (int i = 0; i < 3; i++) {
                    int item = tid + 256 * i;
                    int kk = item >> 6, off = (item & 63) * 2;
                    *(float2*)&sm->u.g.Ws[kk * 128 + off] = wpre[i];
                    *(float2*)&sm->u.g.Zs[kk * 128 + off] = zpre[i];
                }
                __syncthreads();
                if (chunk + 1 < SEGK / CHUNK) {
                    int kb = kBase + (chunk + 1) * CHUNK;
#pragma unroll
                    for (int i = 0; i < 3; i++) {
                        int item = tid + 256 * i;
                        int kk = item >> 6, off = (item & 63) * 2;
                        wpre[i] = *(const float2*)&g_Wt[(size_t)(kb + kk) * MPAD2 + rowBase + off];
                        zpre[i] = __ldcg((const float2*)&g_Z[(kb + kk) * BB + colBase + off]);
                    }
                }
#pragma unroll 3
                for (int kk = 0; kk < CHUNK; kk++) {
                    ulonglong2 w01 = *(const ulonglong2*)&sm->u.g.Ws[kk * 128 + gr0];
                    ulonglong2 w23 = *(const ulonglong2*)&sm->u.g.Ws[kk * 128 + gr0 + 4];
                    float4 za = *(const float4*)&sm->u.g.Zs[kk * 128 + gc0];
                    float4 zb = *(const float4*)&sm->u.g.Zs[kk * 128 + gc0 + 4];
                    unsigned long long z[8];
                    z[0] = pack2(za.x); z[1] = pack2(za.y); z[2] = pack2(za.z); z[3] = pack2(za.w);
                    z[4] = pack2(zb.x); z[5] = pack2(zb.y); z[6] = pack2(zb.z); z[7] = pack2(zb.w);
#pragma unroll
                    for (int c = 0; c < 8; c++) {
                        acc[c][0] = fma2(w01.x, z[c], acc[c][0]);
                        acc[c][1] = fma2(w01.y, z[c], acc[c][1]);
                        acc[c][2] = fma2(w23.x, z[c], acc[c][2]);
                        acc[c][3] = fma2(w23.y, z[c], acc[c][3]);
                    }
                }
            }
#pragma unroll
            for (int c = 0; c < 8; c++) {
                float2 p0 = unpack2(acc[c][0]);
                float2 p1 = unpack2(acc[c][1]);
                float2 p2 = unpack2(acc[c][2]);
                float2 p3 = unpack2(acc[c][3]);
                float* dst = &outbuf[(size_t)(colBase + gc0 + c) * MPAD2 + rowBase + gr0];
                *(float4*)dst       = make_float4(p0.x, p0.y, p1.x, p1.y);
                *(float4*)(dst + 4) = make_float4(p2.x, p2.y, p3.x, p3.y);
            }
        }
        gsync();

        // ---- per-batch phase (old ctx = sm->ctx_s from last attention) ----
        int tok = input[t * BB + b];

        const float* gv = &g_gv[(size_t)tok * MPAD];
        for (int j = tid; j < HID; j += 256) {
            float gi = gv[j];
            float gf = gv[HID + j];
            float gg = gv[2 * HID + j];
            float go = gv[3 * HID + j];
#pragma unroll
            for (int s = 0; s < NSEG; s++) {
                const float* gp = &g_gpart[((size_t)s * BB + b) * MPAD2];
                gi += __ldcg(gp + j);
                gf += __ldcg(gp + HID + j);
                gg += __ldcg(gp + 2 * HID + j);
                go += __ldcg(gp + 3 * HID + j);
            }
            float cc = sigf(gf) * g_c[b * HID + j] + sigf(gi) * tanhf(gg);
            float hh = sigf(go) * tanhf(cc);
            g_c[b * HID + j] = cc;
            sm->h_s[j] = hh;
        }
        __syncthreads();

        for (int v = warp; v < VOCAB; v += 8) {
            float s = 0.0f;
            for (int j = lane; j < HID + VALD; j += 32) {
                float x = (j < HID) ? sm->h_s[j] : sm->ctx_s[j - HID];
                s = fmaf(proj_w[v * (HID + VALD) + j], x, s);
            }
            s = warp_sum(s);
            if (lane == 0) out[((size_t)t * BB + b) * VOCAB + v] = s + proj_b[v];
        }

        attention(sm, b, tid, phi_b);

        for (int d = tid; d < VALD; d += 256) g_Z[d * BB + b] = sm->ctx_s[d];
        for (int j = tid; j < HID; j += 256)  g_Z[(VALD + j) * BB + b] = sm->h_s[j];
        gsync();
    }
}

// ---------------- launch ----------------
extern "C" void kernel_launch(void* const* d_in, const int* in_sizes, int n_in,
                              void* d_out, int out_size) {
    const int*   input     = (const int*)  d_in[0];
    const float* keys      = (const float*)d_in[1];
    const float* values    = (const float*)d_in[2];
    const float* embedding = (const float*)d_in[3];
    const float* phi_w     = (const float*)d_in[4];
    const float* phi_b     = (const float*)d_in[5];
    const float* h0        = (const float*)d_in[6];
    const float* c0        = (const float*)d_in[7];
    const float* W_ih      = (const float*)d_in[8];
    const float* b_ih      = (const float*)d_in[9];
    const float* W_hh      = (const float*)d_in[10];
    const float* b_hh      = (const float*)d_in[11];
    const float* proj_w    = (const float*)d_in[12];
    const float* proj_b    = (const float*)d_in[13];
    float* out = (float*)d_out;

    int smbytes = (int)sizeof(SMem);
    cudaFuncSetAttribute(kmain, cudaFuncAttributeMaxDynamicSharedMemorySize, smbytes);
    kmain<<<NBLK, 256, smbytes>>>(input, keys, values, embedding, phi_w, phi_b,
                                  h0, c0, W_ih, b_ih, W_hh, b_hh, proj_w, proj_b, out);
}

// round 15
// speedup vs baseline: 1.0332x; 1.0332x over previous
#include <cuda_runtime.h>
#include <cuda_fp16.h>

#define EMB   400
#define HID   300
#define HIDP  304
#define PHIS  312
#define KEY   128
#define VALD  128
#define VOCAB 33
#define TT    256
#define BB    256
#define SS    512

#define KP2   432
#define MROWS 1200
#define MPAD  1216
#define MPAD2 1280
#define NBLK  256
#define NSEG  12
#define SEGK  36
#define CHUNK 12
#define NPIECE 240

// ---------------- device scratch ----------------
__device__ float  g_Wt[(size_t)KP2 * MPAD2];
__device__ float  g_Z[KP2 * BB];
__device__ float  g_gpart[(size_t)NSEG * BB * MPAD2];
__device__ float  g_c[BB * HID];
__device__ float  g_gv[VOCAB * MPAD];
__device__ __half g_phiH[KEY * HIDP];
__device__ __half g_keysH[(size_t)BB * KEY * SS];
__device__ __half g_valsH[(size_t)BB * SS * VALD];
__device__ unsigned g_cnt;
__device__ unsigned g_gen;

// ---------------- shared memory ----------------
struct __align__(16) SMem {
    __half phi[KEY * PHIS];
    float h_s[HIDP];
    float q_s[KEY];
    float qp[256];
    float e_s[SS];
    float ctx_s[VALD];
    float red_s[8];
    union {
        struct { float Ws[CHUNK * 128]; float Zs[CHUNK * 128]; } g;
        float e4[4 * SS];
        float part[16 * VALD];
    } u;
};

// ---------------- helpers ----------------
__device__ __forceinline__ float warp_sum(float v) {
#pragma unroll
    for (int m = 16; m > 0; m >>= 1) v += __shfl_xor_sync(0xffffffffu, v, m);
    return v;
}
__device__ __forceinline__ float sigf(float x) { return 1.0f / (1.0f + __expf(-x)); }

__device__ __forceinline__ unsigned long long fma2(unsigned long long a,
                                                   unsigned long long b,
                                                   unsigned long long c) {
    unsigned long long d;
    asm("fma.rn.f32x2 %0, %1, %2, %3;" : "=l"(d) : "l"(a), "l"(b), "l"(c));
    return d;
}
__device__ __forceinline__ unsigned long long pack2(float x) {
    unsigned long long d;
    unsigned int xi = __float_as_uint(x);
    asm("mov.b64 %0, {%1, %1};" : "=l"(d) : "r"(xi));
    return d;
}
__device__ __forceinline__ float2 unpack2(unsigned long long v) {
    unsigned int lo, hi;
    asm("mov.b64 {%0, %1}, %2;" : "=r"(lo), "=r"(hi) : "l"(v));
    return make_float2(__uint_as_float(lo), __uint_as_float(hi));
}

// grid barrier via release/acquire atomics (no CCTL.IVALL — L1 stays warm).
__device__ __forceinline__ void gsync() {
    __syncthreads();
    if (threadIdx.x == 0) {
        unsigned my;
        asm volatile("ld.global.relaxed.gpu.u32 %0, [%1];"
                     : "=r"(my) : "l"(&g_gen) : "memory");
        unsigned rv;
        asm volatile("atom.global.add.acq_rel.gpu.u32 %0, [%1], 1;"
                     : "=r"(rv) : "l"(&g_cnt) : "memory");
        if (rv == NBLK - 1u) {
            asm volatile("st.global.relaxed.gpu.u32 [%0], 0;"
                         :: "l"(&g_cnt) : "memory");
            asm volatile("st.global.release.gpu.u32 [%0], %1;"
                         :: "l"(&g_gen), "r"(my + 1u) : "memory");
        } else {
            unsigned cur;
            do {
                asm volatile("ld.global.acquire.gpu.u32 %0, [%1];"
                             : "=r"(cur) : "l"(&g_gen) : "memory");
            } while (cur == my);
        }
    }
    __syncthreads();
}

// ---------------- attention (8 warps; scalar FMA, no-max softmax) ----------------
__device__ void attention(SMem* sm, int b, int tid, const float* __restrict__ phi_b) {
    int warp = tid >> 5, lane = tid & 31;

    // q matvec: 4 independent accs, float4 h loads
    {
        int kq = tid & 127;
        int hf = tid >> 7;
        const uint4* pw = (const uint4*)&sm->phi[kq * PHIS + hf * (HIDP / 2)];
        const float4* hh = (const float4*)&sm->h_s[hf * (HIDP / 2)];
        float a0 = 0.0f, a1 = 0.0f, a2 = 0.0f, a3 = 0.0f;
#pragma unroll
        for (int u = 0; u < HIDP / 16; u++) {
            uint4 raw = pw[u];
            float4 hb0 = hh[u * 2];
            float4 hb1 = hh[u * 2 + 1];
            float2 f0 = __half22float2(*(const __half2*)&raw.x);
            float2 f1 = __half22float2(*(const __half2*)&raw.y);
            float2 f2 = __half22float2(*(const __half2*)&raw.z);
            float2 f3 = __half22float2(*(const __half2*)&raw.w);
            a0 = fmaf(f0.x, hb0.x, a0); a1 = fmaf(f0.y, hb0.y, a1);
            a2 = fmaf(f1.x, hb0.z, a2); a3 = fmaf(f1.y, hb0.w, a3);
            a0 = fmaf(f2.x, hb1.x, a0); a1 = fmaf(f2.y, hb1.y, a1);
            a2 = fmaf(f3.x, hb1.z, a2); a3 = fmaf(f3.y, hb1.w, a3);
        }
        sm->qp[tid] = (a0 + a1) + (a2 + a3);
    }
    __syncthreads();
    if (tid < KEY) sm->q_s[tid] = sm->qp[tid] + sm->qp[tid + 128] + phi_b[tid];
    __syncthreads();

    // energy partials: thread = (kg, sg): 32 k x 8 s; unroll 16 for MLP
    {
        int kg = tid >> 6;
        int sg = tid & 63;
        const uint4* kp = (const uint4*)&g_keysH[((size_t)b * KEY + kg * 32) * SS + sg * 8];
        float a0 = 0, a1 = 0, a2 = 0, a3 = 0, a4 = 0, a5 = 0, a6 = 0, a7 = 0;
#pragma unroll 16
        for (int k = 0; k < 32; k++) {
            uint4 raw = kp[(size_t)k * (SS / 8)];
            float qk = sm->q_s[kg * 32 + k];
            float2 f0 = __half22float2(*(const __half2*)&raw.x);
            float2 f1 = __half22float2(*(const __half2*)&raw.y);
            float2 f2 = __half22float2(*(const __half2*)&raw.z);
            float2 f3 = __half22float2(*(const __half2*)&raw.w);
            a0 = fmaf(qk, f0.x, a0); a1 = fmaf(qk, f0.y, a1);
            a2 = fmaf(qk, f1.x, a2); a3 = fmaf(qk, f1.y, a3);
            a4 = fmaf(qk, f2.x, a4); a5 = fmaf(qk, f2.y, a5);
            a6 = fmaf(qk, f3.x, a6); a7 = fmaf(qk, f3.y, a7);
        }
        *(float4*)&sm->u.e4[kg * SS + sg * 8]     = make_float4(a0, a1, a2, a3);
        *(float4*)&sm->u.e4[kg * SS + sg * 8 + 4] = make_float4(a4, a5, a6, a7);
    }
    __syncthreads();

    // fused combine + exp + local sum  (energies |e| << 88, no max needed)
    float sum = 0.0f;
    for (int s = tid; s < SS; s += 256) {
        float v = sm->u.e4[s] + sm->u.e4[SS + s] + sm->u.e4[2 * SS + s] + sm->u.e4[3 * SS + s];
        float ev = __expf(v);
        sm->e_s[s] = ev;
        sum += ev;
    }
    sum = warp_sum(sum);
    if (lane == 0) sm->red_s[warp] = sum;
    __syncthreads();
    float tot = sm->red_s[0];
#pragma unroll
    for (int i = 1; i < 8; i++) tot += sm->red_s[i];
    float inv = 1.0f / tot;
    // e4 reads all completed before the sync above; safe to overwrite u.part below

    // ctx; unroll 16 for MLP
    {
        int sh = lane >> 4;
        int dg = lane & 15;
        int sbase = warp * 64 + sh * 32;
        const uint4* vp = (const uint4*)&g_valsH[((size_t)b * SS + sbase) * VALD + dg * 8];
        float a0 = 0, a1 = 0, a2 = 0, a3 = 0, a4 = 0, a5 = 0, a6 = 0, a7 = 0;
#pragma unroll 16
        for (int i = 0; i < 32; i++) {
            uint4 raw = vp[(size_t)i * (VALD / 8)];
            float w = sm->e_s[sbase + i];
            float2 f0 = __half22float2(*(const __half2*)&raw.x);
            float2 f1 = __half22float2(*(const __half2*)&raw.y);
            float2 f2 = __half22float2(*(const __half2*)&raw.z);
            float2 f3 = __half22float2(*(const __half2*)&raw.w);
            a0 = fmaf(w, f0.x, a0); a1 = fmaf(w, f0.y, a1);
            a2 = fmaf(w, f1.x, a2); a3 = fmaf(w, f1.y, a3);
            a4 = fmaf(w, f2.x, a4); a5 = fmaf(w, f2.y, a5);
            a6 = fmaf(w, f3.x, a6); a7 = fmaf(w, f3.y, a7);
        }
        int prow = warp * 2 + sh;
        *(float4*)&sm->u.part[prow * VALD + dg * 8]     = make_float4(a0, a1, a2, a3);
        *(float4*)&sm->u.part[prow * VALD + dg * 8 + 4] = make_float4(a4, a5, a6, a7);
    }
    __syncthreads();
    if (tid < VALD) {
        float s = 0.0f;
#pragma unroll
        for (int w = 0; w < 16; w++) s += sm->u.part[w * VALD + tid];
        sm->ctx_s[tid] = s * inv;
    }
    __syncthreads();
}

// ---------------- persistent kernel ----------------
__global__ void __launch_bounds__(256, 2) kmain(const int* __restrict__ input,
                                                const float* __restrict__ keys,
                                                const float* __restrict__ values,
                                                const float* __restrict__ embedding,
                                                const float* __restrict__ phi_w,
                                                const float* __restrict__ phi_b,
                                                const float* __restrict__ h0,
                                                const float* __restrict__ c0,
                                                const float* __restrict__ W_ih,
                                                const float* __restrict__ b_ih,
                                                const float* __restrict__ W_hh,
                                                const float* __restrict__ b_hh,
                                                const float* __restrict__ proj_w,
                                                const float* __restrict__ proj_b,
                                                float* __restrict__ out) {
    extern __shared__ char smraw[];
    SMem* sm = (SMem*)smraw;

    int bid = blockIdx.x, tid = threadIdx.x;
    int warp = tid >> 5, lane = tid & 31;
    int b = bid;

    // ================= PROLOGUE =================
    {
        int gidx = bid * 256 + tid;
        const int gstr = NBLK * 256;
        for (size_t i = gidx; i < (size_t)KP2 * MPAD2; i += gstr) {
            int k = (int)(i / MPAD2), r = (int)(i % MPAD2);
            float v = 0.0f;
            if (r < MROWS) {
                if (k < VALD)            v = W_ih[r * (EMB + VALD) + EMB + k];
                else if (k < VALD + HID) v = W_hh[r * HID + (k - VALD)];
            }
            g_Wt[i] = v;
        }
        for (int i = gidx; i < KEY * HIDP; i += gstr) {
            int kq = i / HIDP, j = i % HIDP;
            g_phiH[i] = (j < HID) ? __float2half(phi_w[kq * HID + j]) : __half(0.0f);
        }
        for (int i = gidx; i < (KP2 - (VALD + HID)) * BB; i += gstr)
            g_Z[(VALD + HID) * BB + i] = 0.0f;

        float (*ts)[129] = (float (*)[129])smraw;
#pragma unroll 1
        for (int cth = 0; cth < 8; cth++) {
            int s0 = cth * 64;
            __syncthreads();
#pragma unroll
            for (int p = 0; p < 8; p++) {
                int i  = p * 8 + (tid >> 5);
                int k4 = (tid & 31) * 4;
                float4 v = *(const float4*)&keys[((size_t)(s0 + i) * BB + b) * KEY + k4];
                ts[i][k4] = v.x; ts[i][k4 + 1] = v.y; ts[i][k4 + 2] = v.z; ts[i][k4 + 3] = v.w;
            }
            __syncthreads();
#pragma unroll
            for (int p = 0; p < 8; p++) {
                int k  = p * 16 + (tid >> 4);
                int s4 = (tid & 15) * 4;
                __half2 a = __floats2half2_rn(ts[s4][k],     ts[s4 + 1][k]);
                __half2 c = __floats2half2_rn(ts[s4 + 2][k], ts[s4 + 3][k]);
                __half2* dst = (__half2*)&g_keysH[((size_t)b * KEY + k) * SS + s0 + s4];
                dst[0] = a; dst[1] = c;
            }
        }
#pragma unroll 1
        for (int cth = 0; cth < 8; cth++) {
            int s0 = cth * 64;
#pragma unroll
            for (int p = 0; p < 4; p++) {
                int item = p * 256 + tid;
                int row = item >> 4;
                int g   = item & 15;
                const float4* src = (const float4*)&values[((size_t)(s0 + row) * BB + b) * VALD + g * 8];
                float4 v0 = src[0], v1 = src[1];
                __half2 h0h = __floats2half2_rn(v0.x, v0.y);
                __half2 h1h = __floats2half2_rn(v0.z, v0.w);
                __half2 h2h = __floats2half2_rn(v1.x, v1.y);
                __half2 h3h = __floats2half2_rn(v1.z, v1.w);
                *(uint4*)&g_valsH[((size_t)b * SS + s0 + row) * VALD + g * 8] =
                    make_uint4(*(unsigned*)&h0h, *(unsigned*)&h1h, *(unsigned*)&h2h, *(unsigned*)&h3h);
            }
        }
        if (bid < 4 * VOCAB) {
            int v = bid >> 2;
            int rbase = (bid & 3) * 304;
            float* emb_s = (float*)smraw;
            __syncthreads();
            for (int e = tid; e < EMB; e += 256) emb_s[e] = embedding[v * EMB + e];
            __syncthreads();
            for (int r = rbase + warp; r < rbase + 304; r += 8) {
                float s = 0.0f;
                if (r < MROWS) {
                    const float* wr = &W_ih[(size_t)r * (EMB + VALD)];
                    for (int e = lane; e < EMB; e += 32) s = fmaf(wr[e], emb_s[e], s);
                }
                s = warp_sum(s);
                if (lane == 0)
                    g_gv[v * MPAD + r] = (r < MROWS) ? s + b_ih[r] + b_hh[r] : 0.0f;
            }
        }
    }
    gsync();

    // ================= INIT =================
    for (int item = tid; item < KEY * (HIDP / 8); item += 256) {
        int kq = item / (HIDP / 8);
        int u  = item % (HIDP / 8);
        *(uint4*)&sm->phi[kq * PHIS + u * 8] = *(const uint4*)&g_phiH[kq * HIDP + u * 8];
    }

    bool gemmOn = (bid < NPIECE);
    int gTile = bid / NSEG, gSeg = bid % NSEG;
    int rowBase = (gTile % 10) * 128;
    int colBase = (gTile / 10) * 128;
    int kBase = gSeg * SEGK;
    float* outbuf = g_gpart + (size_t)gSeg * (BB * MPAD2);
    int rg = tid & 15, cg = tid >> 4;
    int gr0 = rg * 8, gc0 = cg * 8;

    for (int j = tid; j < HIDP; j += 256) {
        sm->h_s[j] = (j < HID) ? h0[j] : 0.0f;
        if (j < HID) g_c[b * HID + j] = c0[j];
    }
    __syncthreads();
    attention(sm, b, tid, phi_b);
    for (int d = tid; d < VALD; d += 256) g_Z[d * BB + b] = sm->ctx_s[d];
    for (int j = tid; j < HID; j += 256)  g_Z[(VALD + j) * BB + b] = sm->h_s[j];
    gsync();

    // ================= MAIN LOOP =================
    for (int t = 0; t < TT; t++) {
        if (gemmOn) {
            unsigned long long acc[8][4];
#pragma unroll
            for (int c = 0; c < 8; c++)
#pragma unroll
                for (int r = 0; r < 4; r++) acc[c][r] = 0ull;

            float2 wpre[3], zpre[3];
#pragma unroll
            for (int i = 0; i < 3; i++) {
                int item = tid + 256 * i;
                int kk = item >> 6, off = (item & 63) * 2;
                wpre[i] = *(const float2*)&g_Wt[(size_t)(kBase + kk) * MPAD2 + rowBase + off];
                zpre[i] = __ldcg((const float2*)&g_Z[(kBase + kk) * BB + colBase + off]);
            }

#pragma unroll
            for (int chunk = 0; chunk < SEGK / CHUNK; chunk++) {
                __syncthreads();
#pragma unroll
                for (int i = 0; i < 3; i++) {
                    int item = tid + 256 * i;
                    int kk = item >> 6, off = (item & 63) * 2;
                    *(float2*)&sm->u.g.Ws[kk * 128 + off] = wpre[i];
                    *(float2*)&sm->u.g.Zs[kk * 128 + off] = zpre[i];
                }
                __syncthreads();
                if (chunk + 1 < SEGK / CHUNK) {
                    int kb = kBase + (chunk + 1) * CHUNK;
#pragma unroll
                    for (int i = 0; i < 3; i++) {
                        int item = tid + 256 * i;
                        int kk = item >> 6, off = (item & 63) * 2;
                        wpre[i] = *(const float2*)&g_Wt[(size_t)(kb + kk) * MPAD2 + rowBase + off];
                        zpre[i] = __ldcg((const float2*)&g_Z[(kb + kk) * BB + colBase + off]);
                    }
                }
#pragma unroll 3
                for (int kk = 0; kk < CHUNK; kk++) {
                    ulonglong2 w01 = *(const ulonglong2*)&sm->u.g.Ws[kk * 128 + gr0];
                    ulonglong2 w23 = *(const ulonglong2*)&sm->u.g.Ws[kk * 128 + gr0 + 4];
                    float4 za = *(const float4*)&sm->u.g.Zs[kk * 128 + gc0];
                    float4 zb = *(const float4*)&sm->u.g.Zs[kk * 128 + gc0 + 4];
                    unsigned long long z[8];
                    z[0] = pack2(za.x); z[1] = pack2(za.y); z[2] = pack2(za.z); z[3] = pack2(za.w);
                    z[4] = pack2(zb.x); z[5] = pack2(zb.y); z[6] = pack2(zb.z); z[7] = pack2(zb.w);
#pragma unroll
                    for (int c = 0; c < 8; c++) {
                        acc[c][0] = fma2(w01.x, z[c], acc[c][0]);
                        acc[c][1] = fma2(w01.y, z[c], acc[c][1]);
                        acc[c][2] = fma2(w23.x, z[c], acc[c][2]);
                        acc[c][3] = fma2(w23.y, z[c], acc[c][3]);
                    }
                }
            }
#pragma unroll
            for (int c = 0; c < 8; c++) {
                float2 p0 = unpack2(acc[c][0]);
                float2 p1 = unpack2(acc[c][1]);
                float2 p2 = unpack2(acc[c][2]);
                float2 p3 = unpack2(acc[c][3]);
                float* dst = &outbuf[(size_t)(colBase + gc0 + c) * MPAD2 + rowBase + gr0];
                *(float4*)dst       = make_float4(p0.x, p0.y, p1.x, p1.y);
                *(float4*)(dst + 4) = make_float4(p2.x, p2.y, p3.x, p3.y);
            }
        }
        gsync();

        // ---- per-batch phase (old ctx = sm->ctx_s from last attention) ----
        int tok = input[t * BB + b];

        const float* gv = &g_gv[(size_t)tok * MPAD];
        for (int j = tid; j < HID; j += 256) {
            float gi = gv[j];
            float gf = gv[HID + j];
            float gg = gv[2 * HID + j];
            float go = gv[3 * HID + j];
#pragma unroll
            for (int s = 0; s < NSEG; s++) {
                const float* gp = &g_gpart[((size_t)s * BB + b) * MPAD2];
                gi += __ldcg(gp + j);
                gf += __ldcg(gp + HID + j);
                gg += __ldcg(gp + 2 * HID + j);
                go += __ldcg(gp + 3 * HID + j);
            }
            float cc = sigf(gf) * g_c[b * HID + j] + sigf(gi) * tanhf(gg);
            float hh = sigf(go) * tanhf(cc);
            g_c[b * HID + j] = cc;
            sm->h_s[j] = hh;
        }
        __syncthreads();

        for (int v = warp; v < VOCAB; v += 8) {
            float s = 0.0f;
            for (int j = lane; j < HID + VALD; j += 32) {
                float x = (j < HID) ? sm->h_s[j] : sm->ctx_s[j - HID];
                s = fmaf(proj_w[v * (HID + VALD) + j], x, s);
            }
            s = warp_sum(s);
            if (lane == 0) out[((size_t)t * BB + b) * VOCAB + v] = s + proj_b[v];
        }

        attention(sm, b, tid, phi_b);

        for (int d = tid; d < VALD; d += 256) g_Z[d * BB + b] = sm->ctx_s[d];
        for (int j = tid; j < HID; j += 256)  g_Z[(VALD + j) * BB + b] = sm->h_s[j];
        gsync();
    }
}

// ---------------- launch ----------------
extern "C" void kernel_launch(void* const* d_in, const int* in_sizes, int n_in,
                              void* d_out, int out_size) {
    const int*   input     = (const int*)  d_in[0];
    const float* keys      = (const float*)d_in[1];
    const float* values    = (const float*)d_in[2];
    const float* embedding = (const float*)d_in[3];
    const float* phi_w     = (const float*)d_in[4];
    const float* phi_b     = (const float*)d_in[5];
    const float* h0        = (const float*)d_in[6];
    const float* c0        = (const float*)d_in[7];
    const float* W_ih      = (const float*)d_in[8];
    const float* b_ih      = (const float*)d_in[9];
    const float* W_hh      = (const float*)d_in[10];
    const float* b_hh      = (const float*)d_in[11];
    const float* proj_w    = (const float*)d_in[12];
    const float* proj_b    = (const float*)d_in[13];
    float* out = (float*)d_out;

    int smbytes = (int)sizeof(SMem);
    cudaFuncSetAttribute(kmain, cudaFuncAttributeMaxDynamicSharedMemorySize, smbytes);
    kmain<<<NBLK, 256, smbytes>>>(input, keys, values, embedding, phi_w, phi_b,
                                  h0, c0, W_ih, b_ih, W_hh, b_hh, proj_w, proj_b, out);
}